// round 13
// baseline (speedup 1.0000x reference)
#include <cuda_runtime.h>
#include <cuda_bf16.h>
#include <cuda_fp16.h>
#include <math.h>

#define F_DIM   128
#define HEADS   8
#define CH      16
#define MAXN    50048
#define MAXE    860160

typedef unsigned long long ull;

#define FMA_F32X2(d, a, b, c) \
    asm("fma.rn.f32x2 %0, %1, %2, %3;" : "=l"(d) : "l"(a), "l"(b), "l"(c))
#define UNPACK_F32X2F(lo, hi, in) \
    asm("mov.b64 {%0, %1}, %2;" : "=f"(lo), "=f"(hi) : "l"(in))

__device__ __forceinline__ ull dupf(float v) {
    ull r;
    asm("mov.b64 %0, {%1, %1};" : "=l"(r) : "r"(__float_as_uint(v)));
    return r;
}

// ---------------- device scratch ----------------
__device__ __half g_hh[MAXN * F_DIM];    // GEMM output in fp16 (gather-optimized)
__device__ float g_t[MAXN * F_DIM];      // layer0 aggregated output (fp32)
__device__ float g_asrc[MAXN * HEADS];
__device__ float g_adst[MAXN * HEADS];
__device__ int   g_deg[MAXN];
__device__ int   g_off[MAXN + 1];
__device__ int   g_cur[MAXN];
__device__ int   g_csr[MAXE];
__device__ float g_pool[MAXN * CH];
__device__ float g_bnsum[F_DIM];
__device__ float g_bnsq[F_DIM];
__device__ float g_bnscale[F_DIM];
__device__ float g_bnshift[F_DIM];

// ---------------- utility kernels ----------------
__global__ void zero_ints(int* p, int n) {
    int i = blockIdx.x * blockDim.x + threadIdx.x;
    if (i < n) p[i] = 0;
}
__global__ void zero_bn() {   // zero both bnsum & bnsq in one launch
    int i = threadIdx.x;
    if (i < F_DIM) { g_bnsum[i] = 0.f; g_bnsq[i] = 0.f; }
}

// ---------------- CSR build ----------------
__global__ void hist_kernel(const int* __restrict__ ei, int E, int n) {
    int i = blockIdx.x * blockDim.x + threadIdx.x;
    int tot = E + n;
    if (i >= tot) return;
    int d = (i < E) ? ei[E + i] : (i - E);
    atomicAdd(&g_deg[d], 1);
}

// two-level shfl scan, 1024 threads
__global__ void scan_kernel(int n) {
    __shared__ int wsum[32];
    int tid = threadIdx.x;
    int lane = tid & 31, wid = tid >> 5;
    int chunk = (n + 1023) >> 10;
    int b = tid * chunk;
    int e = min(n, b + chunk);
    int s = 0;
    for (int i = b; i < e; i++) s += g_deg[i];
    int v = s;
#pragma unroll
    for (int o = 1; o < 32; o <<= 1) {
        int t = __shfl_up_sync(0xFFFFFFFFu, v, o);
        if (lane >= o) v += t;
    }
    if (lane == 31) wsum[wid] = v;
    __syncthreads();
    if (wid == 0) {
        int w = wsum[lane];
#pragma unroll
        for (int o = 1; o < 32; o <<= 1) {
            int t = __shfl_up_sync(0xFFFFFFFFu, w, o);
            if (lane >= o) w += t;
        }
        wsum[lane] = w;
    }
    __syncthreads();
    int excl = v - s + ((wid > 0) ? wsum[wid - 1] : 0);
    int run = excl;
    for (int i = b; i < e; i++) {
        g_off[i] = run;
        g_cur[i] = run;
        run += g_deg[i];
    }
    if (tid == 0) g_off[n] = wsum[31];
}

__global__ void scatter_kernel(const int* __restrict__ ei, int E, int n) {
    int i = blockIdx.x * blockDim.x + threadIdx.x;
    int tot = E + n;
    if (i >= tot) return;
    int s, d;
    if (i < E) { s = ei[i]; d = ei[E + i]; }
    else       { s = d = i - E; }
    int p = atomicAdd(&g_cur[d], 1);
    g_csr[p] = s;
}

// ---------------- fused GEMM (f32x2 packed FFMA) + attention-score epilogue --
__device__ __forceinline__ float bnelu_f(float v, int f) {
    float y = v * g_bnscale[f] + g_bnshift[f];
    return (y > 0.f) ? y : expm1f(y);
}

// smem: Bs fp32 [128*128] (64KB) + As2 dup-f32x2 [16*128] ull (16KB) = 80KB
#define GEMM_SMEM (128 * 128 * 4 + 16 * 128 * 8)

template <bool BNELU>
__global__ __launch_bounds__(256, 2) void gemm_fused(
    const float* __restrict__ A, const float* __restrict__ B,
    __half* __restrict__ Ch,
    const float* __restrict__ attS, const float* __restrict__ attD, int M)
{
    extern __shared__ float smem[];
    float* Bs = smem;                            // [128][128] fp32
    ull* As2 = (ull*)(smem + 128 * 128);         // [16][128] duplicated pairs
    int tid = threadIdx.x;
    int row0 = blockIdx.x * 128;
    int tr = (tid >> 4) * 8;
    int tc = (tid & 15) * 8;

    // load full B into smem (issued before first barrier)
    for (int i = tid * 4; i < 128 * 128; i += 1024) {
        *(float4*)(Bs + i) = *(const float4*)(B + i);
    }

    int ar = tid >> 1;
    int ak = (tid & 1) * 8;
    int arow = row0 + ar;
    bool aval = arow < M;
    const float* Aptr = A + (size_t)arow * F_DIM;

    float4 pa0 = make_float4(0.f, 0.f, 0.f, 0.f), pa1 = pa0;
    if (aval) {
        pa0 = *(const float4*)(Aptr + ak);
        pa1 = *(const float4*)(Aptr + ak + 4);
        if (BNELU) {
            pa0.x = bnelu_f(pa0.x, ak + 0); pa0.y = bnelu_f(pa0.y, ak + 1);
            pa0.z = bnelu_f(pa0.z, ak + 2); pa0.w = bnelu_f(pa0.w, ak + 3);
            pa1.x = bnelu_f(pa1.x, ak + 4); pa1.y = bnelu_f(pa1.y, ak + 5);
            pa1.z = bnelu_f(pa1.z, ak + 6); pa1.w = bnelu_f(pa1.w, ak + 7);
        }
    }

    ull acc2[8][4];
#pragma unroll
    for (int i = 0; i < 8; i++)
#pragma unroll
        for (int j = 0; j < 4; j++) acc2[i][j] = 0ULL;

#pragma unroll 1
    for (int c = 0; c < 8; c++) {
        __syncthreads();   // prev compute done (and B resident on first iter)
        As2[(ak + 0) * 128 + ar] = dupf(pa0.x);
        As2[(ak + 1) * 128 + ar] = dupf(pa0.y);
        As2[(ak + 2) * 128 + ar] = dupf(pa0.z);
        As2[(ak + 3) * 128 + ar] = dupf(pa0.w);
        As2[(ak + 4) * 128 + ar] = dupf(pa1.x);
        As2[(ak + 5) * 128 + ar] = dupf(pa1.y);
        As2[(ak + 6) * 128 + ar] = dupf(pa1.z);
        As2[(ak + 7) * 128 + ar] = dupf(pa1.w);
        __syncthreads();
        if (c < 7 && aval) {
            int k0 = (c + 1) * 16;
            pa0 = *(const float4*)(Aptr + k0 + ak);
            pa1 = *(const float4*)(Aptr + k0 + ak + 4);
            if (BNELU) {
                pa0.x = bnelu_f(pa0.x, k0 + ak + 0); pa0.y = bnelu_f(pa0.y, k0 + ak + 1);
                pa0.z = bnelu_f(pa0.z, k0 + ak + 2); pa0.w = bnelu_f(pa0.w, k0 + ak + 3);
                pa1.x = bnelu_f(pa1.x, k0 + ak + 4); pa1.y = bnelu_f(pa1.y, k0 + ak + 5);
                pa1.z = bnelu_f(pa1.z, k0 + ak + 6); pa1.w = bnelu_f(pa1.w, k0 + ak + 7);
            }
        }
#pragma unroll
        for (int k = 0; k < 16; k++) {
            const ull* a2r = As2 + k * 128;
            const float* bsr = Bs + (c * 16 + k) * 128;
            ulonglong2 aa0 = *(const ulonglong2*)(a2r + tr);
            ulonglong2 aa1 = *(const ulonglong2*)(a2r + tr + 2);
            ulonglong2 aa2 = *(const ulonglong2*)(a2r + tr + 4);
            ulonglong2 aa3 = *(const ulonglong2*)(a2r + tr + 6);
            ulonglong2 bb0 = *(const ulonglong2*)(bsr + tc);
            ulonglong2 bb1 = *(const ulonglong2*)(bsr + tc + 4);
            ull a2[8] = {aa0.x, aa0.y, aa1.x, aa1.y, aa2.x, aa2.y, aa3.x, aa3.y};
            ull b2[4] = {bb0.x, bb0.y, bb1.x, bb1.y};
#pragma unroll
            for (int i = 0; i < 8; i++) {
#pragma unroll
                for (int jp = 0; jp < 4; jp++) {
                    FMA_F32X2(acc2[i][jp], a2[i], b2[jp], acc2[i][jp]);
                }
            }
        }
    }

    // unpack accumulators
    float acc[8][8];
#pragma unroll
    for (int i = 0; i < 8; i++)
#pragma unroll
        for (int jp = 0; jp < 4; jp++)
            UNPACK_F32X2F(acc[i][2 * jp], acc[i][2 * jp + 1], acc2[i][jp]);

    // epilogue: write C (fp16) and head-wise attention partial dots (fp32)
    int head = tc >> 4;
    int off = tc & 15;   // 0 or 8
    float as8[8], ad8[8];
#pragma unroll
    for (int j = 0; j < 8; j++) {
        as8[j] = __ldg(attS + head * CH + off + j);
        ad8[j] = __ldg(attD + head * CH + off + j);
    }
#pragma unroll
    for (int i = 0; i < 8; i++) {
        int r = row0 + tr + i;
        float s = 0.f, d = 0.f;
#pragma unroll
        for (int j = 0; j < 8; j++) {
            s += acc[i][j] * as8[j];
            d += acc[i][j] * ad8[j];
        }
        s += __shfl_xor_sync(0xFFFFFFFFu, s, 1);
        d += __shfl_xor_sync(0xFFFFFFFFu, d, 1);
        if (r < M) {
            __half2 p0 = __floats2half2_rn(acc[i][0], acc[i][1]);
            __half2 p1 = __floats2half2_rn(acc[i][2], acc[i][3]);
            __half2 p2 = __floats2half2_rn(acc[i][4], acc[i][5]);
            __half2 p3 = __floats2half2_rn(acc[i][6], acc[i][7]);
            uint4 pk;
            pk.x = *(unsigned*)&p0; pk.y = *(unsigned*)&p1;
            pk.z = *(unsigned*)&p2; pk.w = *(unsigned*)&p3;
            *(uint4*)(Ch + (size_t)r * F_DIM + tc) = pk;
            if (!(tid & 1)) {
                g_asrc[r * HEADS + head] = s;
                g_adst[r * HEADS + head] = d;
            }
        }
    }
}

// ---------------- single-pass softmax + aggregation (warp per node) ----------------
// 2-edge software pipeline: both loads issued before either consume -> MLP x2.
template <bool MEAN_HEADS>
__global__ void agg_kernel(const __half* __restrict__ h,
                           const float* __restrict__ bias,
                           float* __restrict__ out, int n) {
    int warp = (blockIdx.x * blockDim.x + threadIdx.x) >> 5;
    int lane = threadIdx.x & 31;
    if (warp >= n) return;
    int node = warp;
    int head = lane >> 2;
    int fo = lane * 4;

    int beg = g_off[node];
    int end = g_off[node + 1];
    float adst_v = g_adst[node * HEADS + head];

    float ssum = 0.f;
    float4 acc = make_float4(0.f, 0.f, 0.f, 0.f);

    int i = beg;
    for (; i + 1 < end; i += 2) {
        int s0 = g_csr[i];
        int s1 = g_csr[i + 1];
        float e0 = g_asrc[s0 * HEADS + head];
        float e1 = g_asrc[s1 * HEADS + head];
        uint2 r0 = *(const uint2*)(h + (size_t)s0 * F_DIM + fo);
        uint2 r1 = *(const uint2*)(h + (size_t)s1 * F_DIM + fo);
        e0 += adst_v; e0 = (e0 > 0.f) ? e0 : 0.2f * e0;
        e1 += adst_v; e1 = (e1 > 0.f) ? e1 : 0.2f * e1;
        float w0 = __expf(e0);
        float w1 = __expf(e1);
        ssum += w0 + w1;
        float2 a01 = __half22float2(*(__half2*)&r0.x);
        float2 a23 = __half22float2(*(__half2*)&r0.y);
        float2 b01 = __half22float2(*(__half2*)&r1.x);
        float2 b23 = __half22float2(*(__half2*)&r1.y);
        acc.x += w0 * a01.x + w1 * b01.x;
        acc.y += w0 * a01.y + w1 * b01.y;
        acc.z += w0 * a23.x + w1 * b23.x;
        acc.w += w0 * a23.y + w1 * b23.y;
    }
    if (i < end) {
        int s0 = g_csr[i];
        float e0 = g_asrc[s0 * HEADS + head] + adst_v;
        e0 = (e0 > 0.f) ? e0 : 0.2f * e0;
        float w0 = __expf(e0);
        ssum += w0;
        uint2 r0 = *(const uint2*)(h + (size_t)s0 * F_DIM + fo);
        float2 a01 = __half22float2(*(__half2*)&r0.x);
        float2 a23 = __half22float2(*(__half2*)&r0.y);
        acc.x += w0 * a01.x;
        acc.y += w0 * a01.y;
        acc.z += w0 * a23.x;
        acc.w += w0 * a23.y;
    }
    float inv = 1.0f / (ssum + 1e-16f);
    acc.x *= inv; acc.y *= inv; acc.z *= inv; acc.w *= inv;

    if (MEAN_HEADS) {
#pragma unroll
        for (int o = 4; o < 32; o <<= 1) {
            acc.x += __shfl_xor_sync(0xFFFFFFFFu, acc.x, o);
            acc.y += __shfl_xor_sync(0xFFFFFFFFu, acc.y, o);
            acc.z += __shfl_xor_sync(0xFFFFFFFFu, acc.z, o);
            acc.w += __shfl_xor_sync(0xFFFFFFFFu, acc.w, o);
        }
        if (lane < 4) {
            int cbase = lane * 4;
            float4 r;
            r.x = acc.x * 0.125f + __ldg(&bias[cbase + 0]);
            r.y = acc.y * 0.125f + __ldg(&bias[cbase + 1]);
            r.z = acc.z * 0.125f + __ldg(&bias[cbase + 2]);
            r.w = acc.w * 0.125f + __ldg(&bias[cbase + 3]);
            *(float4*)(out + (size_t)node * CH + cbase) = r;
        }
    } else {
        float4 r;
        r.x = acc.x + __ldg(&bias[fo + 0]);
        r.y = acc.y + __ldg(&bias[fo + 1]);
        r.z = acc.z + __ldg(&bias[fo + 2]);
        r.w = acc.w + __ldg(&bias[fo + 3]);
        *(float4*)(out + (size_t)node * F_DIM + fo) = r;
    }
}

// ---------------- batchnorm stats ----------------
template <int F>
__global__ void bn_stats(const float* __restrict__ x, int n, int rows_per_block) {
    __shared__ float ss[256], qq[256];
    int tid = threadIdx.x;
    int f = tid % F;
    int rsub = tid / F;
    const int rstride = 256 / F;
    int r0 = blockIdx.x * rows_per_block;
    int r1 = min(n, r0 + rows_per_block);
    float s = 0.f, q = 0.f;
    for (int r = r0 + rsub; r < r1; r += rstride) {
        float v = x[(size_t)r * F + f];
        s += v;
        q += v * v;
    }
    ss[tid] = s;
    qq[tid] = q;
    __syncthreads();
    if (tid < F) {
        float S = ss[tid], Q = qq[tid];
        for (int k = tid + F; k < 256; k += F) { S += ss[k]; Q += qq[k]; }
        atomicAdd(&g_bnsum[tid], S);
        atomicAdd(&g_bnsq[tid], Q);
    }
}

// ---------------- BN finalize: precompute scale/shift ----------------
__global__ void bn_finalize(const float* __restrict__ gamma,
                            const float* __restrict__ beta, float invn) {
    int f = threadIdx.x;
    float mu = g_bnsum[f] * invn;
    float var = g_bnsq[f] * invn - mu * mu;
    float sc = rsqrtf(var + 1e-5f) * gamma[f];
    g_bnscale[f] = sc;
    g_bnshift[f] = beta[f] - mu * sc;
}

// ---------------- final: BN(F=16) + classifier [16x2] ----------------
__global__ void final_kernel(const float* __restrict__ gamma,
                             const float* __restrict__ beta,
                             const float* __restrict__ Wc,
                             const float* __restrict__ bc,
                             float* __restrict__ out, int n, float invn) {
    int node = blockIdx.x * blockDim.x + threadIdx.x;
    if (node >= n) return;
    float l0 = __ldg(&bc[0]);
    float l1 = __ldg(&bc[1]);
#pragma unroll
    for (int c = 0; c < CH; c++) {
        float mu = g_bnsum[c] * invn;
        float var = g_bnsq[c] * invn - mu * mu;
        float sc = rsqrtf(var + 1e-5f) * __ldg(&gamma[c]);
        float y = (g_pool[(size_t)node * CH + c] - mu) * sc + __ldg(&beta[c]);
        l0 += y * __ldg(&Wc[c * 2 + 0]);
        l1 += y * __ldg(&Wc[c * 2 + 1]);
    }
    out[node * 2 + 0] = l0;
    out[node * 2 + 1] = l1;
}

// ---------------- launch ----------------
extern "C" void kernel_launch(void* const* d_in, const int* in_sizes, int n_in,
                              void* d_out, int out_size) {
    const float* x        = (const float*)d_in[0];
    const int*   ei       = (const int*)d_in[1];
    const float* W0       = (const float*)d_in[2];
    const float* att_src0 = (const float*)d_in[3];
    const float* att_dst0 = (const float*)d_in[4];
    const float* b0       = (const float*)d_in[5];
    const float* gamma0   = (const float*)d_in[6];
    const float* beta0    = (const float*)d_in[7];
    const float* W1       = (const float*)d_in[8];
    const float* att_src1 = (const float*)d_in[9];
    const float* att_dst1 = (const float*)d_in[10];
    const float* b1       = (const float*)d_in[11];
    const float* gamma1   = (const float*)d_in[12];
    const float* beta1    = (const float*)d_in[13];
    const float* Wc       = (const float*)d_in[14];
    const float* bc       = (const float*)d_in[15];
    float* out = (float*)d_out;

    int N = in_sizes[0] / F_DIM;
    int E = in_sizes[1] / 2;
    int ET = E + N;
    float invn = 1.0f / (float)N;

    __half* g_hh_p;
    float *g_t_p, *g_pool_p;
    int *g_deg_p;
    cudaGetSymbolAddress((void**)&g_hh_p, g_hh);
    cudaGetSymbolAddress((void**)&g_t_p, g_t);
    cudaGetSymbolAddress((void**)&g_pool_p, g_pool);
    cudaGetSymbolAddress((void**)&g_deg_p, g_deg);

    cudaFuncSetAttribute(gemm_fused<false>,
                         cudaFuncAttributeMaxDynamicSharedMemorySize, GEMM_SMEM);
    cudaFuncSetAttribute(gemm_fused<true>,
                         cudaFuncAttributeMaxDynamicSharedMemorySize, GEMM_SMEM);

    int gemm_grid = (N + 127) / 128;

    // side stream for CSR build, forked/joined with events (capture-legal pattern)
    cudaStream_t s2;
    cudaStreamCreateWithFlags(&s2, cudaStreamNonBlocking);
    cudaEvent_t evFork, evJoin;
    cudaEventCreateWithFlags(&evFork, cudaEventDisableTiming);
    cudaEventCreateWithFlags(&evJoin, cudaEventDisableTiming);

    cudaEventRecord(evFork, 0);
    cudaStreamWaitEvent(s2, evFork, 0);

    // ---- CSR build on side stream (independent of GEMM0) ----
    zero_ints<<<(N + 255) / 256, 256, 0, s2>>>(g_deg_p, N);
    hist_kernel<<<(ET + 255) / 256, 256, 0, s2>>>(ei, E, N);
    scan_kernel<<<1, 1024, 0, s2>>>(N);
    scatter_kernel<<<(ET + 255) / 256, 256, 0, s2>>>(ei, E, N);
    cudaEventRecord(evJoin, s2);

    // ---- layer 0: GEMM(+attn scores) on main stream, concurrent with CSR ----
    gemm_fused<false><<<gemm_grid, 256, GEMM_SMEM>>>(x, W0, g_hh_p,
                                                     att_src0, att_dst0, N);
    cudaStreamWaitEvent(0, evJoin, 0);   // join: agg needs CSR + GEMM0
    agg_kernel<false><<<(N * 32 + 255) / 256, 256>>>(g_hh_p, b0, g_t_p, N);

    zero_bn<<<1, 256>>>();
    bn_stats<F_DIM><<<(N + 127) / 128, 256>>>(g_t_p, N, 128);
    bn_finalize<<<1, F_DIM>>>(gamma0, beta0, invn);

    // ---- layer 1: GEMM with fused BN+ELU on A (+attn scores) -> agg ----
    gemm_fused<true><<<gemm_grid, 256, GEMM_SMEM>>>(g_t_p, W1, g_hh_p,
                                                    att_src1, att_dst1, N);
    agg_kernel<true><<<(N * 32 + 255) / 256, 256>>>(g_hh_p, b1, g_pool_p, N);

    zero_bn<<<1, 256>>>();
    bn_stats<CH><<<(N + 127) / 128, 256>>>(g_pool_p, N, 128);
    final_kernel<<<(N + 255) / 256, 256>>>(gamma1, beta1, Wc, bc, out, N, invn);
    // streams/events intentionally not destroyed here: destroying capture-
    // participating resources mid-capture is illegal; leak is a few host handles
    // on the 2 non-replay calls.
}